// round 9
// baseline (speedup 1.0000x reference)
#include <cuda_runtime.h>
#include <math.h>

#define SS   4096      // 64*64
#define SSS  262144    // 64^3
#define CH   64

typedef unsigned long long u64;

// Scratch (device globals). att1/att2 are batch-interleaved: element (c*SSS+s)
// is a float2 = (batch0, batch1). float4 decl for 16B alignment.
__device__ float4 g_att1[CH*SSS/2];
__device__ float4 g_att2[CH*SSS/2];
__device__ float2 g_pooled2[2*SSS];    // [ic={mean,max}][s] -> (b0,b1)
__device__ float  g_gate[2*2*SSS];     // [b][{g0,g1}][s]

__device__ __forceinline__ u64 pk2(float lo, float hi) {
    u64 r; asm("mov.b64 %0, {%1, %2};" : "=l"(r) : "f"(lo), "f"(hi)); return r;
}
__device__ __forceinline__ void ffma2(u64& d, u64 a, u64 b) {
    asm("fma.rn.f32x2 %0, %1, %2, %0;" : "+l"(d) : "l"(a), "l"(b));
}
__device__ __forceinline__ float2 up2(u64 v) {
    float2 f; asm("mov.b64 {%0, %1}, %2;" : "=f"(f.x), "=f"(f.y) : "l"(v)); return f;
}

// ---------------- conv1: depthwise 5x5x5, pad 2, both batches packed --------
// 64 threads = lxh(4) x hz(2) x ly(8). Tile z16 y8 x8. Each thread: 2 adjacent
// x outputs (sliding-window col reuse) x 8 z. x-stride 21 (odd), plane stride
// 253 (8*253 === 8 mod 16) -> all 16-lane phases hit 16 distinct bank pairs.
#define XS1 21
#define PS1 253
__global__ __launch_bounds__(64) void k_conv1(const float* __restrict__ x,
                                              const float* __restrict__ w1,
                                              const float* __restrict__ b1) {
    __shared__ float2 sh[20*PS1];                // 40480 B
    __shared__ float2 swt[125];

    const int bx = blockIdx.x, c = blockIdx.y;
    const int tz = bx & 3, ty = (bx >> 2) & 7, tx = bx >> 5;
    const int z0 = tz*16, y0 = ty*8, x0 = tx*8;
    const int tid = threadIdx.x;

    const float* __restrict__ x0p = x + (size_t)c * SSS;
    const float* __restrict__ x1p = x + (size_t)(CH + c) * SSS;

    for (int s = tid; s < 125; s += 64) { float w = w1[c*125 + s]; swt[s] = make_float2(w, w); }

    // load 20z x 12y x 12x halo tile
#pragma unroll
    for (int k = 0; k < 3; k++) {
        const int p = tid + 64*k;
        if (p < 144) {
            const int sy = p / 12, sx = p % 12;
            const int gy = y0 - 2 + sy, gx = x0 - 2 + sx;
            const bool vyx = ((unsigned)gy < 64u) && ((unsigned)gx < 64u);
            const int shb = sy*XS1 + sx;
            const int gb  = gy*64 + gx;
#pragma unroll 4
            for (int sz = 0; sz < 20; sz++) {
                const int gz = z0 - 2 + sz;
                float2 v = make_float2(0.f, 0.f);
                if (vyx && (unsigned)gz < 64u) {
                    const int o = gz*SS + gb;
                    v.x = x0p[o]; v.y = x1p[o];
                }
                sh[sz*PS1 + shb] = v;
            }
        }
    }
    __syncthreads();

    const int lxh = tid & 3, hz = (tid >> 2) & 1, ly = tid >> 3;
    const int xo = 2*lxh, zb = 8*hz;

    u64 acc0[8], acc1[8];
    const float bias = b1[c];
    const u64 bpk = pk2(bias, bias);
#pragma unroll
    for (int z = 0; z < 8; z++) { acc0[z] = bpk; acc1[z] = bpk; }

#pragma unroll 1
    for (int ky = 0; ky < 5; ky++) {
        const float2* bp = &sh[zb*PS1 + (ly + ky)*XS1 + xo];
        u64 cc[2][12];
#pragma unroll
        for (int j = 0; j < 12; j++) {
            cc[0][j] = *(const u64*)&bp[j*PS1];
            cc[1][j] = *(const u64*)&bp[j*PS1 + 1];
        }
#pragma unroll
        for (int kx = 0; kx < 5; kx++) {
#pragma unroll
            for (int kz = 0; kz < 5; kz++) {
                const u64 w = *(const u64*)&swt[kz*25 + ky*5 + kx];
#pragma unroll
                for (int z = 0; z < 8; z++) {
                    ffma2(acc0[z], cc[kx & 1][z + kz], w);
                    ffma2(acc1[z], cc[(kx + 1) & 1][z + kz], w);
                }
            }
            if (kx < 4) {
#pragma unroll
                for (int j = 0; j < 12; j++)
                    cc[kx & 1][j] = *(const u64*)&bp[j*PS1 + kx + 2];
            }
        }
    }

    float2* __restrict__ oc = (float2*)g_att1 + (size_t)c * SSS;
#pragma unroll
    for (int z = 0; z < 8; z++) {
        float2 lo = up2(acc0[z]), hi = up2(acc1[z]);
        float4 v = make_float4(lo.x, lo.y, hi.x, hi.y);
        *(float4*)&oc[(z0 + zb + z)*SS + (y0 + ly)*64 + (x0 + xo)] = v;
    }
}

// ---------------- conv2: depthwise 7x7x7, dilation 3, pad 9 -----------------
// Residue decomposition (mod 3) -> dense 7-tap conv on subsampled grid.
// 64 threads = lxh(4) x hz(2) x ly(8); each thread: 2 adjacent x outputs x 11 z
// with sliding-window col reuse. y-stride 15 (odd), plane stride 216
// (11*216 === 8 mod 16) -> conflict-free LDS.64. Weights staged per-ky into a
// 49-entry smem slab (static total 48776 B <= 48 KB).
#define ZS2 216
__global__ __launch_bounds__(64) void k_conv2(const float* __restrict__ w2,
                                              const float* __restrict__ b2) {
    __shared__ float2 sh[28*ZS2];                // 48384 B
    __shared__ float2 swt[49];                   // per-ky slab, 392 B

    const int blk = blockIdx.x;                  // 27 residues * 9 yx tiles
    const int c = blockIdx.y;
    const int res = blk / 9, t = blk % 9;
    const int rz = res / 9, ry = (res / 3) % 3, rx = res % 3;
    const int tyi = t / 3, txi = t % 3;
    const int Lz = (rz == 0) ? 22 : 21;
    const int Ly = (ry == 0) ? 22 : 21;
    const int Lx = (rx == 0) ? 22 : 21;

    const int tid = threadIdx.x;
    const float2* __restrict__ icp = (const float2*)g_att1 + (size_t)c * SSS;
    const float* __restrict__ w2c = w2 + c*343;

    const int uy0 = tyi*8, ux0 = txi*8;
    // load 28z x 14y x 14x subgrid halo tile
#pragma unroll
    for (int k = 0; k < 4; k++) {
        const int p = tid + 64*k;
        if (p < 196) {
            const int sy = p / 14, sx = p % 14;
            const int gy = ry + 3*(uy0 + sy - 3);
            const int gx = rx + 3*(ux0 + sx - 3);
            const bool vyx = ((unsigned)gy < 64u) && ((unsigned)gx < 64u);
            const int shb = sy*15 + sx;
            const int gb  = gy*64 + gx;
#pragma unroll 4
            for (int sz = 0; sz < 28; sz++) {
                const int gz = rz + 3*(sz - 3);
                float2 v = make_float2(0.f, 0.f);
                if (vyx && (unsigned)gz < 64u)
                    v = icp[gz*SS + gb];
                sh[sz*ZS2 + shb] = v;
            }
        }
    }

    const int lxh = tid & 3, hz = (tid >> 2) & 1, ly = tid >> 3;
    const int xo = 2*lxh, zb = 11*hz;
    const int uy = uy0 + ly;

    u64 acc0[11], acc1[11];
    const float bias = b2[c];
    const u64 bpk = pk2(bias, bias);
#pragma unroll
    for (int l = 0; l < 11; l++) { acc0[l] = bpk; acc1[l] = bpk; }

#pragma unroll 1
    for (int ky = 0; ky < 7; ky++) {
        __syncthreads();                         // protect swt from prev iter readers
        if (tid < 49) {
            const int kz = tid / 7, kx = tid % 7;
            float w = __ldg(&w2c[kz*49 + ky*7 + kx]);
            swt[tid] = make_float2(w, w);
        }
        __syncthreads();

        const float2* bp = &sh[zb*ZS2 + (ly + ky)*15 + xo];
        u64 cc[2][17];
#pragma unroll
        for (int j = 0; j < 17; j++) {
            cc[0][j] = *(const u64*)&bp[j*ZS2];
            cc[1][j] = *(const u64*)&bp[j*ZS2 + 1];
        }
#pragma unroll
        for (int kx = 0; kx < 7; kx++) {
#pragma unroll
            for (int kz = 0; kz < 7; kz++) {
                const u64 w = *(const u64*)&swt[kz*7 + kx];
#pragma unroll
                for (int l = 0; l < 11; l++) {
                    ffma2(acc0[l], cc[kx & 1][l + kz], w);
                    ffma2(acc1[l], cc[(kx + 1) & 1][l + kz], w);
                }
            }
            if (kx < 6) {
#pragma unroll
                for (int j = 0; j < 17; j++)
                    cc[kx & 1][j] = *(const u64*)&bp[j*ZS2 + kx + 2];
            }
        }
    }

    if (uy < Ly) {
        float2* __restrict__ oc = (float2*)g_att2 + (size_t)c*SSS;
        const int gy = ry + 3*uy;
        const int ux_a = ux0 + xo, ux_b = ux_a + 1;
        const int gx_a = rx + 3*ux_a, gx_b = gx_a + 3;
        const bool va = (ux_a < Lx), vb = (ux_b < Lx);
#pragma unroll
        for (int l = 0; l < 11; l++) {
            const int u = zb + l;
            if (u < Lz) {
                const int o = (rz + 3*u)*SS + gy*64;
                if (va) *(u64*)&oc[o + gx_a] = acc0[l];
                if (vb) *(u64*)&oc[o + gx_b] = acc1[l];
            }
        }
    }
}

// ---------------- pool: channel mean + max over [att1; att2], both batches --
__global__ __launch_bounds__(256) void k_pool() {
    const int s = blockIdx.x * 256 + threadIdx.x;       // over SSS
    const float2* p1 = (const float2*)g_att1 + s;
    const float2* p2 = (const float2*)g_att2 + s;
    float s0 = 0.f, s1 = 0.f, m0 = -INFINITY, m1 = -INFINITY;
#pragma unroll 8
    for (int c = 0; c < 64; c++) {
        float2 v = p1[(size_t)c*SSS];
        s0 += v.x; s1 += v.y; m0 = fmaxf(m0, v.x); m1 = fmaxf(m1, v.y);
    }
#pragma unroll 8
    for (int c = 0; c < 64; c++) {
        float2 v = p2[(size_t)c*SSS];
        s0 += v.x; s1 += v.y; m0 = fmaxf(m0, v.x); m1 = fmaxf(m1, v.y);
    }
    g_pooled2[s]       = make_float2(s0 * (1.f/128.f), s1 * (1.f/128.f));
    g_pooled2[SSS + s] = make_float2(m0, m1);
}

// ---------------- gate: 2->2 conv 7x7x7 pad 3, sigmoid (scalar, per batch) --
__global__ __launch_bounds__(128) void k_gate(const float* __restrict__ ws,
                                              const float* __restrict__ bs) {
    const int tile = blockIdx.x;                 // tz(8) ty(4) tx(8) = 256
    const int b = blockIdx.y;
    const int tz = tile >> 5, ty = (tile >> 3) & 3, tx = tile & 7;
    const int z0 = tz*8, y0 = ty*16, x0 = tx*8;

    __shared__ float sh[2*14*22*14];
    __shared__ float swt[1372];
    const int tid = threadIdx.x;

    for (int s = tid; s < 1372; s += 128) swt[s] = ws[s];
    for (int s = tid; s < 2*14*22*14; s += 128) {
        int icc = s / 4312, r = s % 4312;
        int sz = r / 308, r2 = r % 308, sy = r2 / 14, sx = r2 % 14;
        int gz = z0-3+sz, gy = y0-3+sy, gx = x0-3+sx;
        float v = 0.f;
        if ((unsigned)gz < 64u && (unsigned)gy < 64u && (unsigned)gx < 64u) {
            float2 p = g_pooled2[icc*SSS + gz*SS + gy*64 + gx];
            v = b ? p.y : p.x;
        }
        sh[s] = v;
    }
    __syncthreads();

    const int ly = tid >> 3, lx = tid & 7;
    float acc0[8], acc1[8];
    const float bias0 = bs[0], bias1 = bs[1];
#pragma unroll
    for (int z = 0; z < 8; z++) { acc0[z] = bias0; acc1[z] = bias1; }

#pragma unroll 1
    for (int icc = 0; icc < 2; icc++)
#pragma unroll 1
    for (int ky = 0; ky < 7; ky++)
#pragma unroll 1
    for (int kx = 0; kx < 7; kx++) {
        float col[14];
#pragma unroll
        for (int j = 0; j < 14; j++)
            col[j] = sh[icc*4312 + j*308 + (ly+ky)*14 + lx + kx];
#pragma unroll
        for (int kz = 0; kz < 7; kz++) {
            const float w0 = swt[icc*343 + kz*49 + ky*7 + kx];
            const float w1 = swt[686 + icc*343 + kz*49 + ky*7 + kx];
#pragma unroll
            for (int z = 0; z < 8; z++) {
                acc0[z] = fmaf(col[z+kz], w0, acc0[z]);
                acc1[z] = fmaf(col[z+kz], w1, acc1[z]);
            }
        }
    }

    float* g0 = g_gate + (size_t)b*2*SSS;
#pragma unroll
    for (int z = 0; z < 8; z++) {
        const int o = (z0+z)*SS + (y0+ly)*64 + (x0+lx);
        g0[o]       = 1.f/(1.f + __expf(-acc0[z]));
        g0[SSS + o] = 1.f/(1.f + __expf(-acc1[z]));
    }
}

// ---------------- combine: out = att1*g0 + att2*g1 + x ----------------------
__global__ __launch_bounds__(256) void k_combine(const float* __restrict__ x,
                                                 float* __restrict__ out) {
    const int i = blockIdx.x * 256 + threadIdx.x;      // 8,388,608 threads
    const int c = i >> 17;                              // SSS/2 per channel
    const int s = (i & 131071) << 1;
    const float4 a1 = *(const float4*)((const float*)g_att1 + ((size_t)c*SSS + s)*2);
    const float4 a2 = *(const float4*)((const float*)g_att2 + ((size_t)c*SSS + s)*2);

    // batch 0
    {
        const float2 xv = *(const float2*)(x + (size_t)c*SSS + s);
        const float2 g0 = *(const float2*)(g_gate + s);
        const float2 g1 = *(const float2*)(g_gate + SSS + s);
        float2 o;
        o.x = fmaf(a1.x, g0.x, fmaf(a2.x, g1.x, xv.x));
        o.y = fmaf(a1.z, g0.y, fmaf(a2.z, g1.y, xv.y));
        *(float2*)(out + (size_t)c*SSS + s) = o;
    }
    // batch 1
    {
        const float2 xv = *(const float2*)(x + (size_t)(CH + c)*SSS + s);
        const float2 g0 = *(const float2*)(g_gate + 2*SSS + s);
        const float2 g1 = *(const float2*)(g_gate + 3*SSS + s);
        float2 o;
        o.x = fmaf(a1.y, g0.x, fmaf(a2.y, g1.x, xv.x));
        o.y = fmaf(a1.w, g0.y, fmaf(a2.w, g1.y, xv.y));
        *(float2*)(out + (size_t)(CH + c)*SSS + s) = o;
    }
}

extern "C" void kernel_launch(void* const* d_in, const int* in_sizes, int n_in,
                              void* d_out, int out_size) {
    const float* x  = (const float*)d_in[0];
    const float* w1 = (const float*)d_in[1];
    const float* b1 = (const float*)d_in[2];
    const float* w2 = (const float*)d_in[3];
    const float* b2 = (const float*)d_in[4];
    const float* ws = (const float*)d_in[5];
    const float* bs = (const float*)d_in[6];
    float* out = (float*)d_out;

    k_conv1<<<dim3(256, 64), 64>>>(x, w1, b1);
    k_conv2<<<dim3(243, 64), 64>>>(w2, b2);
    k_pool<<<1024, 256>>>();
    k_gate<<<dim3(256, 2), 128>>>(ws, bs);
    k_combine<<<32768, 256>>>(x, out);
}